// round 14
// baseline (speedup 1.0000x reference)
#include <cuda_runtime.h>
#include <cuda_fp16.h>
#include <cstdint>

#define B   32
#define L   1024
#define D   256
#define INV_TEMP (1.0f/16.0f)

// ---------------------------------------------------------------------------
// Scratch (fp16)
// ---------------------------------------------------------------------------
__device__ __half g_qh [B * L * D];   // q hi   [B,L,D]
__device__ __half g_ql [B * L * D];   // q lo   [B,L,D]  (GEMM1 B-side only)
__device__ __half g_qth[B * D * L];   // q^T hi [B,D,L]  (pv B-side)
__device__ __half g_ph [B * L * L];   // softmax(P) fp16

// upper-triangle 128x128 block pair decode (8x8 blocks -> 36 pairs)
__constant__ uint8_t c_bi[36] = {0,0,0,0,0,0,0,0, 1,1,1,1,1,1,1, 2,2,2,2,2,2,
                                 3,3,3,3,3, 4,4,4,4, 5,5,5, 6,6, 7};
__constant__ uint8_t c_bj[36] = {0,1,2,3,4,5,6,7, 1,2,3,4,5,6,7, 2,3,4,5,6,7,
                                 3,4,5,6,7, 4,5,6,7, 5,6,7, 6,7, 7};

__device__ __forceinline__ float neg_inf() { return __int_as_float(0xff800000); }

__device__ __forceinline__ uint32_t smem_to_u32(const void* p) {
    uint32_t a;
    asm("{ .reg .u64 t; cvta.to.shared.u64 t, %1; cvt.u32.u64 %0, t; }" : "=r"(a) : "l"(p));
    return a;
}

#define SWZ(x) ((x) ^ (((x) >> 3) & 0x70))

__device__ __forceinline__ void ldsm_x4(uint32_t& r0, uint32_t& r1, uint32_t& r2, uint32_t& r3,
                                        uint32_t addr) {
    asm volatile("ldmatrix.sync.aligned.m8n8.x4.shared.b16 {%0,%1,%2,%3}, [%4];"
                 : "=r"(r0), "=r"(r1), "=r"(r2), "=r"(r3) : "r"(addr));
}

__device__ __forceinline__ void mma_f16(float& c0, float& c1, float& c2, float& c3,
                                        uint32_t a0, uint32_t a1, uint32_t a2, uint32_t a3,
                                        uint32_t b0, uint32_t b1) {
    asm volatile("mma.sync.aligned.m16n8k16.row.col.f32.f16.f16.f32 "
                 "{%0,%1,%2,%3}, {%4,%5,%6,%7}, {%8,%9}, {%0,%1,%2,%3};"
                 : "+f"(c0), "+f"(c1), "+f"(c2), "+f"(c3)
                 : "r"(a0), "r"(a1), "r"(a2), "r"(a3), "r"(b0), "r"(b1));
}

#define CP_ASYNC_16(dst, src) \
    asm volatile("cp.async.cg.shared.global [%0], [%1], 16;" :: "r"(dst), "l"(src))
#define CP_ASYNC_COMMIT() asm volatile("cp.async.commit_group;" ::: "memory")
#define CP_ASYNC_WAIT(n)  asm volatile("cp.async.wait_group %0;" :: "n"(n) : "memory")

// ---------------------------------------------------------------------------
// Kernel A: split q -> fp16 hi/lo + transposed hi copy.
// ---------------------------------------------------------------------------
__global__ void __launch_bounds__(256) split_q_kernel(const float* __restrict__ q) {
    const int b  = blockIdx.z;
    const int d0 = blockIdx.x * 32;
    const int l0 = blockIdx.y * 32;
    const float* Q = q + (size_t)b * L * D;
    __shared__ float t[32][33];
    const int tx = threadIdx.x, ty = threadIdx.y;

    #pragma unroll
    for (int i = 0; i < 4; i++) {
        const int r = ty + i * 8;
        const float v = Q[(size_t)(l0 + r) * D + d0 + tx];
        t[r][tx] = v;
        __half h  = __float2half_rn(v);
        __half lo = __float2half_rn(v - __half2float(h));
        const size_t idx = (size_t)b * L * D + (size_t)(l0 + r) * D + d0 + tx;
        g_qh[idx] = h;
        g_ql[idx] = lo;
    }
    __syncthreads();
    #pragma unroll
    for (int i = 0; i < 4; i++) {
        const int r = ty + i * 8;
        const float v = t[tx][r];
        const size_t idx = (size_t)b * D * L + (size_t)(d0 + r) * L + l0 + tx;
        g_qth[idx] = __float2half_rn(v);
    }
}

// ---------------------------------------------------------------------------
// Generic tile loader: ROWS x 64 fp16, 128B swizzled rows, NT threads.
// ---------------------------------------------------------------------------
template <int ROWS, int NT>
__device__ __forceinline__ void issue_tile(const __half* __restrict__ src,
                                           int row0, int ld, int k0,
                                           uint32_t smem_tile, int tid) {
    #pragma unroll
    for (int i = 0; i < (ROWS * 8) / NT; i++) {
        const int chunk = tid + i * NT;
        const int row = chunk >> 3;
        const int c16 = chunk & 7;
        const __half* g = src + (size_t)(row0 + row) * ld + k0 + c16 * 8;
        CP_ASYNC_16(smem_tile + SWZ((uint32_t)(row * 128 + c16 * 16)), g);
    }
}

// ===========================================================================
// GEMM1 (symmetric): S = Q@Q^T, 2-term fp16 (qh @ qh + qh @ ql == qh @ q).
// CTA 128x128, 8 warps (2x4), warp tile 64x32, 2-stage.
// stage = A 16KB + Bh 16KB + Bl 16KB = 48KB; 96KB -> 2 CTAs/SM.
// grid (36, 1, B); direct + transposed mirror write for off-diagonal pairs.
// ===========================================================================
#define G1_T 16384
#define G1_STAGE (3 * G1_T)              // 48KB
#define G1_SMEM (2 * G1_STAGE)           // 96KB
#define G1_A  0
#define G1_BH G1_T
#define G1_BL (2 * G1_T)

__device__ __forceinline__ void g1_issue_stage(
        const __half* pQh, const __half* pQl,
        int m0, int n0, int k0, uint32_t st, int tid) {
    issue_tile<128, 256>(pQh, m0, D, k0, st + G1_A, tid);
    issue_tile<128, 256>(pQh, n0, D, k0, st + G1_BH, tid);
    issue_tile<128, 256>(pQl, n0, D, k0, st + G1_BL, tid);
    CP_ASYNC_COMMIT();
}

__global__ void __launch_bounds__(256, 2)
gemm_qqt_sym_kernel(const __half* __restrict__ Qh, const __half* __restrict__ Ql,
                    float* __restrict__ S) {
    extern __shared__ char smem[];
    const uint32_t sb = smem_to_u32(smem);
    const int tid = threadIdx.x, wid = tid >> 5, lid = tid & 31;
    const int b  = blockIdx.z;
    const int bi = c_bi[blockIdx.x];
    const int bj = c_bj[blockIdx.x];
    const int m0 = bi * 128;
    const int n0 = bj * 128;

    const __half* pQh = Qh + (size_t)b * L * D;
    const __half* pQl = Ql + (size_t)b * L * D;

    const int rowbase = (wid & 1) * 64;     // 2x4 warp grid, warp tile 64x32
    const int colbase = (wid >> 1) * 32;
    const int lrow = lid & 15;
    const uint32_t lkoff = (uint32_t)((lid >> 4) * 16);

    float acc[4][4][4];
    #pragma unroll
    for (int mt = 0; mt < 4; mt++)
        #pragma unroll
        for (int nt = 0; nt < 4; nt++)
            #pragma unroll
            for (int r = 0; r < 4; r++) acc[mt][nt][r] = 0.0f;

    const int nch = D >> 6;   // 4
    g1_issue_stage(pQh, pQl, m0, n0, 0, sb, tid);

    for (int c = 0; c < nch; c++) {
        if (c + 1 < nch) {
            g1_issue_stage(pQh, pQl, m0, n0, (c + 1) << 6,
                           sb + (uint32_t)((c + 1) & 1) * G1_STAGE, tid);
            CP_ASYNC_WAIT(1);
        } else {
            CP_ASYNC_WAIT(0);
        }
        __syncthreads();

        const uint32_t st = sb + (uint32_t)(c & 1) * G1_STAGE;
        const uint32_t aA = st + G1_A;
        const uint32_t bH = st + G1_BH;
        const uint32_t bL = st + G1_BL;

        #pragma unroll
        for (int ks = 0; ks < 4; ks++) {
            const uint32_t kb = (uint32_t)(ks * 32) + lkoff;
            uint32_t ah[4][4];
            #pragma unroll
            for (int mt = 0; mt < 4; mt++) {
                const uint32_t boff = (uint32_t)((rowbase + mt * 16 + lrow) * 128) + kb;
                ldsm_x4(ah[mt][0], ah[mt][1], ah[mt][2], ah[mt][3], aA + SWZ(boff));
            }
            #pragma unroll
            for (int np = 0; np < 2; np++) {
                const uint32_t boff = (uint32_t)((colbase + np * 16 + lrow) * 128) + kb;
                uint32_t bh[4], bl[4];
                ldsm_x4(bh[0], bh[1], bh[2], bh[3], bH + SWZ(boff));
                ldsm_x4(bl[0], bl[1], bl[2], bl[3], bL + SWZ(boff));
                #pragma unroll
                for (int mt = 0; mt < 4; mt++) {
                    float* c0 = acc[mt][np * 2 + 0];
                    float* c1 = acc[mt][np * 2 + 1];
                    mma_f16(c0[0], c0[1], c0[2], c0[3],
                            ah[mt][0], ah[mt][1], ah[mt][2], ah[mt][3], bh[0], bh[2]);
                    mma_f16(c1[0], c1[1], c1[2], c1[3],
                            ah[mt][0], ah[mt][1], ah[mt][2], ah[mt][3], bh[1], bh[3]);
                    mma_f16(c0[0], c0[1], c0[2], c0[3],
                            ah[mt][0], ah[mt][1], ah[mt][2], ah[mt][3], bl[0], bl[2]);
                    mma_f16(c1[0], c1[1], c1[2], c1[3],
                            ah[mt][0], ah[mt][1], ah[mt][2], ah[mt][3], bl[1], bl[3]);
                }
            }
        }
        __syncthreads();
    }

    // mask + scale
    #pragma unroll
    for (int mt = 0; mt < 4; mt++)
        #pragma unroll
        for (int nt = 0; nt < 4; nt++)
            #pragma unroll
            for (int r = 0; r < 4; r++) {
                float v = acc[mt][nt][r];
                acc[mt][nt][r] = (v == 0.0f) ? neg_inf() : v * INV_TEMP;
            }

    float* pS = S + (size_t)b * L * L;
    const int trow = lid >> 2;
    const int tcol = (lid & 3) * 2;

    // direct write
    #pragma unroll
    for (int mt = 0; mt < 4; mt++) {
        #pragma unroll
        for (int nt = 0; nt < 4; nt++) {
            const int row = m0 + rowbase + mt * 16 + trow;
            const int col = n0 + colbase + nt * 8 + tcol;
            *(float2*)(pS + (size_t)row * L + col) =
                make_float2(acc[mt][nt][0], acc[mt][nt][1]);
            *(float2*)(pS + (size_t)(row + 8) * L + col) =
                make_float2(acc[mt][nt][2], acc[mt][nt][3]);
        }
    }

    if (bi != bj) {
        // mirror: stage 128x128 transpose in smem (rows padded to 132 floats)
        float* smemT = (float*)smem;
        #pragma unroll
        for (int mt = 0; mt < 4; mt++) {
            #pragma unroll
            for (int nt = 0; nt < 4; nt++) {
                const int i0 = rowbase + mt * 16 + trow;
                const int j0 = colbase + nt * 8 + tcol;
                smemT[(j0 + 0) * 132 + i0]     = acc[mt][nt][0];
                smemT[(j0 + 1) * 132 + i0]     = acc[mt][nt][1];
                smemT[(j0 + 0) * 132 + i0 + 8] = acc[mt][nt][2];
                smemT[(j0 + 1) * 132 + i0 + 8] = acc[mt][nt][3];
            }
        }
        __syncthreads();
        const int j    = tid >> 1;          // 0..127
        const int half = (tid & 1) * 64;
        float* dst = pS + (size_t)(n0 + j) * L + m0 + half;
        const float* srcrow = smemT + j * 132 + half;
        #pragma unroll
        for (int u = 0; u < 16; u++) {
            *(float4*)(dst + u * 4) = *(const float4*)(srcrow + u * 4);
        }
    }
}

// ===========================================================================
// GEMM2: O = Ph @ qt_h (single term). CTA 128x128, 8 warps (2x4),
// warp tile 64x32, 2-stage. stage = A 16KB + B 16KB = 32KB; 64KB -> 2 CTAs/SM.
// grid (D/128, L/128, B) = (2, 8, 32)
// ===========================================================================
#define PV_T 16384
#define PV_STAGE (2 * PV_T)              // 32KB
#define PV_SMEM (2 * PV_STAGE)           // 64KB
#define PV_A  0
#define PV_B  PV_T

__device__ __forceinline__ void pv_issue_stage(
        const __half* pPh, const __half* pBh,
        int m0, int n0, int k0, uint32_t st, int tid) {
    issue_tile<128, 256>(pPh, m0, L, k0, st + PV_A, tid);
    issue_tile<128, 256>(pBh, n0, L, k0, st + PV_B, tid);
    CP_ASYNC_COMMIT();
}

__global__ void __launch_bounds__(256, 2)
gemm_pv_kernel(const __half* __restrict__ Ph,
               const __half* __restrict__ Bh,
               float* __restrict__ O) {
    extern __shared__ char smem[];
    const uint32_t sb = smem_to_u32(smem);
    const int tid = threadIdx.x, wid = tid >> 5, lid = tid & 31;
    const int b  = blockIdx.z;
    const int m0 = blockIdx.y * 128;
    const int n0 = blockIdx.x * 128;

    const __half* pPh = Ph + (size_t)b * L * L;
    const __half* pBh = Bh + (size_t)b * D * L;

    const int rowbase = (wid & 1) * 64;
    const int colbase = (wid >> 1) * 32;
    const int lrow = lid & 15;
    const uint32_t lkoff = (uint32_t)((lid >> 4) * 16);

    float acc[4][4][4];
    #pragma unroll
    for (int mt = 0; mt < 4; mt++)
        #pragma unroll
        for (int nt = 0; nt < 4; nt++)
            #pragma unroll
            for (int r = 0; r < 4; r++) acc[mt][nt][r] = 0.0f;

    const int nch = L >> 6;   // 16

    pv_issue_stage(pPh, pBh, m0, n0, 0, sb, tid);

    for (int c = 0; c < nch; c++) {
        if (c + 1 < nch) {
            pv_issue_stage(pPh, pBh, m0, n0, (c + 1) << 6,
                           sb + (uint32_t)((c + 1) & 1) * PV_STAGE, tid);
            CP_ASYNC_WAIT(1);
        } else {
            CP_ASYNC_WAIT(0);
        }
        __syncthreads();

        const uint32_t st = sb + (uint32_t)(c & 1) * PV_STAGE;
        const uint32_t aA = st + PV_A;
        const uint32_t bB = st + PV_B;

        #pragma unroll
        for (int ks = 0; ks < 4; ks++) {
            const uint32_t kb = (uint32_t)(ks * 32) + lkoff;
            uint32_t ah[4][4];
            #pragma unroll
            for (int mt = 0; mt < 4; mt++) {
                const uint32_t boff = (uint32_t)((rowbase + mt * 16 + lrow) * 128) + kb;
                ldsm_x4(ah[mt][0], ah[mt][1], ah[mt][2], ah[mt][3], aA + SWZ(boff));
            }
            #pragma unroll
            for (int np = 0; np < 2; np++) {
                const uint32_t boff = (uint32_t)((colbase + np * 16 + lrow) * 128) + kb;
                uint32_t bh[4];
                ldsm_x4(bh[0], bh[1], bh[2], bh[3], bB + SWZ(boff));
                #pragma unroll
                for (int mt = 0; mt < 4; mt++) {
                    float* c0 = acc[mt][np * 2 + 0];
                    float* c1 = acc[mt][np * 2 + 1];
                    mma_f16(c0[0], c0[1], c0[2], c0[3],
                            ah[mt][0], ah[mt][1], ah[mt][2], ah[mt][3], bh[0], bh[2]);
                    mma_f16(c1[0], c1[1], c1[2], c1[3],
                            ah[mt][0], ah[mt][1], ah[mt][2], ah[mt][3], bh[1], bh[3]);
                }
            }
        }
        __syncthreads();
    }

    float* pO = O + (size_t)b * L * D;
    const int trow = lid >> 2;
    const int tcol = (lid & 3) * 2;
    #pragma unroll
    for (int mt = 0; mt < 4; mt++) {
        #pragma unroll
        for (int nt = 0; nt < 4; nt++) {
            const int row = m0 + rowbase + mt * 16 + trow;
            const int col = n0 + colbase + nt * 8 + tcol;
            *(float2*)(pO + (size_t)row * D + col) =
                make_float2(acc[mt][nt][0], acc[mt][nt][1]);
            *(float2*)(pO + (size_t)(row + 8) * D + col) =
                make_float2(acc[mt][nt][2], acc[mt][nt][3]);
        }
    }
}

// ---------------------------------------------------------------------------
// softmax: one warp per row, barrier-free. Emits P fp32 + fp16.
// ---------------------------------------------------------------------------
__global__ void __launch_bounds__(256) softmax_kernel(float* __restrict__ attn) {
    const int wid = threadIdx.x >> 5, lid = threadIdx.x & 31;
    const size_t row = (size_t)blockIdx.x * 8 + wid;
    float* p = attn + row * L;
    __half* ph = g_ph + row * L;

    float4 v[8];
    #pragma unroll
    for (int i = 0; i < 8; i++) v[i] = ((const float4*)p)[lid + 32 * i];

    float m = neg_inf();
    #pragma unroll
    for (int i = 0; i < 8; i++) {
        m = fmaxf(m, fmaxf(fmaxf(v[i].x, v[i].y), fmaxf(v[i].z, v[i].w)));
    }
    #pragma unroll
    for (int o = 16; o > 0; o >>= 1) m = fmaxf(m, __shfl_xor_sync(0xffffffffu, m, o));

    if (m == neg_inf()) {
        const float4 z4 = make_float4(0.f, 0.f, 0.f, 0.f);
        const uint2 z2 = make_uint2(0u, 0u);
        #pragma unroll
        for (int i = 0; i < 8; i++) {
            ((float4*)p)[lid + 32 * i] = z4;
            ((uint2*)ph)[lid + 32 * i] = z2;
        }
        return;
    }

    float s = 0.0f;
    #pragma unroll
    for (int i = 0; i < 8; i++) {
        v[i].x = __expf(v[i].x - m);
        v[i].y = __expf(v[i].y - m);
        v[i].z = __expf(v[i].z - m);
        v[i].w = __expf(v[i].w - m);
        s += (v[i].x + v[i].y) + (v[i].z + v[i].w);
    }
    #pragma unroll
    for (int o = 16; o > 0; o >>= 1) s += __shfl_xor_sync(0xffffffffu, s, o);
    const float inv = 1.0f / s;

    #pragma unroll
    for (int i = 0; i < 8; i++) {
        v[i].x *= inv; v[i].y *= inv; v[i].z *= inv; v[i].w *= inv;
        ((float4*)p)[lid + 32 * i] = v[i];

        __half2 hp0 = __floats2half2_rn(v[i].x, v[i].y);
        __half2 hp1 = __floats2half2_rn(v[i].z, v[i].w);
        uint2 hu;
        hu.x = *(uint32_t*)&hp0;
        hu.y = *(uint32_t*)&hp1;
        ((uint2*)ph)[lid + 32 * i] = hu;
    }
}

// ---------------------------------------------------------------------------
// Launch
// ---------------------------------------------------------------------------
extern "C" void kernel_launch(void* const* d_in, const int* in_sizes, int n_in,
                              void* d_out, int out_size) {
    const float* q = (const float*)d_in[0];
    float* out  = (float*)d_out;
    float* attn = (float*)d_out + (size_t)B * L * D;

    void *qh, *ql, *qth, *ph;
    cudaGetSymbolAddress(&qh,  g_qh);
    cudaGetSymbolAddress(&ql,  g_ql);
    cudaGetSymbolAddress(&qth, g_qth);
    cudaGetSymbolAddress(&ph,  g_ph);

    cudaFuncSetAttribute(gemm_qqt_sym_kernel, cudaFuncAttributeMaxDynamicSharedMemorySize, G1_SMEM);
    cudaFuncSetAttribute(gemm_pv_kernel,      cudaFuncAttributeMaxDynamicSharedMemorySize, PV_SMEM);

    dim3 gs(D / 32, L / 32, B);
    split_q_kernel<<<gs, dim3(32, 8)>>>(q);

    dim3 g1(36, 1, B);
    gemm_qqt_sym_kernel<<<g1, 256, G1_SMEM>>>(
        (const __half*)qh, (const __half*)ql, attn);

    softmax_kernel<<<B * L / 8, 256>>>(attn);

    dim3 g2(D / 128, L / 128, B);
    gemm_pv_kernel<<<g2, 256, PV_SMEM>>>(
        (const __half*)ph, (const __half*)qth, out);
}

// round 15
// speedup vs baseline: 1.0750x; 1.0750x over previous
#include <cuda_runtime.h>
#include <cuda_fp16.h>
#include <cstdint>

#define B   32
#define L   1024
#define D   256
#define INV_TEMP (1.0f/16.0f)

// ---------------------------------------------------------------------------
// Scratch (fp16)
// ---------------------------------------------------------------------------
__device__ __half g_qh [B * L * D];
__device__ __half g_ql [B * L * D];
__device__ __half g_qth[B * D * L];
__device__ __half g_ph [B * L * L];

// symmetric tile decode: 128-row block i, 64-col block j64, j64 >= 2i (72 tiles)
__constant__ uint8_t c_ti[72] = {
    0,0,0,0,0,0,0,0,0,0,0,0,0,0,0,0,
    1,1,1,1,1,1,1,1,1,1,1,1,1,1,
    2,2,2,2,2,2,2,2,2,2,2,2,
    3,3,3,3,3,3,3,3,3,3,
    4,4,4,4,4,4,4,4,
    5,5,5,5,5,5,
    6,6,6,6,
    7,7};
__constant__ uint8_t c_tj[72] = {
    0,1,2,3,4,5,6,7,8,9,10,11,12,13,14,15,
    2,3,4,5,6,7,8,9,10,11,12,13,14,15,
    4,5,6,7,8,9,10,11,12,13,14,15,
    6,7,8,9,10,11,12,13,14,15,
    8,9,10,11,12,13,14,15,
    10,11,12,13,14,15,
    12,13,14,15,
    14,15};

__device__ __forceinline__ float neg_inf() { return __int_as_float(0xff800000); }

__device__ __forceinline__ uint32_t smem_to_u32(const void* p) {
    uint32_t a;
    asm("{ .reg .u64 t; cvta.to.shared.u64 t, %1; cvt.u32.u64 %0, t; }" : "=r"(a) : "l"(p));
    return a;
}

#define SWZ(x) ((x) ^ (((x) >> 3) & 0x70))

__device__ __forceinline__ void ldsm_x4(uint32_t& r0, uint32_t& r1, uint32_t& r2, uint32_t& r3,
                                        uint32_t addr) {
    asm volatile("ldmatrix.sync.aligned.m8n8.x4.shared.b16 {%0,%1,%2,%3}, [%4];"
                 : "=r"(r0), "=r"(r1), "=r"(r2), "=r"(r3) : "r"(addr));
}

__device__ __forceinline__ void mma_f16(float& c0, float& c1, float& c2, float& c3,
                                        uint32_t a0, uint32_t a1, uint32_t a2, uint32_t a3,
                                        uint32_t b0, uint32_t b1) {
    asm volatile("mma.sync.aligned.m16n8k16.row.col.f32.f16.f16.f32 "
                 "{%0,%1,%2,%3}, {%4,%5,%6,%7}, {%8,%9}, {%0,%1,%2,%3};"
                 : "+f"(c0), "+f"(c1), "+f"(c2), "+f"(c3)
                 : "r"(a0), "r"(a1), "r"(a2), "r"(a3), "r"(b0), "r"(b1));
}

#define CP_ASYNC_16(dst, src) \
    asm volatile("cp.async.cg.shared.global [%0], [%1], 16;" :: "r"(dst), "l"(src))
#define CP_ASYNC_COMMIT() asm volatile("cp.async.commit_group;" ::: "memory")
#define CP_ASYNC_WAIT(n)  asm volatile("cp.async.wait_group %0;" :: "n"(n) : "memory")

// ---------------------------------------------------------------------------
// Kernel A: split q -> fp16 hi/lo + transposed hi copy.
// ---------------------------------------------------------------------------
__global__ void __launch_bounds__(256) split_q_kernel(const float* __restrict__ q) {
    const int b  = blockIdx.z;
    const int d0 = blockIdx.x * 32;
    const int l0 = blockIdx.y * 32;
    const float* Q = q + (size_t)b * L * D;
    __shared__ float t[32][33];
    const int tx = threadIdx.x, ty = threadIdx.y;

    #pragma unroll
    for (int i = 0; i < 4; i++) {
        const int r = ty + i * 8;
        const float v = Q[(size_t)(l0 + r) * D + d0 + tx];
        t[r][tx] = v;
        __half h  = __float2half_rn(v);
        __half lo = __float2half_rn(v - __half2float(h));
        const size_t idx = (size_t)b * L * D + (size_t)(l0 + r) * D + d0 + tx;
        g_qh[idx] = h;
        g_ql[idx] = lo;
    }
    __syncthreads();
    #pragma unroll
    for (int i = 0; i < 4; i++) {
        const int r = ty + i * 8;
        const float v = t[tx][r];
        const size_t idx = (size_t)b * D * L + (size_t)(d0 + r) * L + l0 + tx;
        g_qth[idx] = __float2half_rn(v);
    }
}

// ---------------------------------------------------------------------------
// Generic tile loader: ROWS x 64 fp16, 128B swizzled rows, NT threads.
// ---------------------------------------------------------------------------
template <int ROWS, int NT>
__device__ __forceinline__ void issue_tile(const __half* __restrict__ src,
                                           int row0, int ld, int k0,
                                           uint32_t smem_tile, int tid) {
    #pragma unroll
    for (int i = 0; i < (ROWS * 8) / NT; i++) {
        const int chunk = tid + i * NT;
        const int row = chunk >> 3;
        const int c16 = chunk & 7;
        const __half* g = src + (size_t)(row0 + row) * ld + k0 + c16 * 8;
        CP_ASYNC_16(smem_tile + SWZ((uint32_t)(row * 128 + c16 * 16)), g);
    }
}

// ===========================================================================
// GEMM1 (symmetric): S = Q@Q^T, 2-term fp16 (qh @ qh + qh @ ql == qh @ q).
// CTA tile 128x64, 8 warps (4x2), warp tile 32x32, 3-stage.
// stage = A 16KB + Bh 8KB + Bl 8KB = 32KB; 96KB -> 2 CTAs/SM.
// grid (72, 1, B). One __syncthreads per chunk (3-stage rotation).
// ===========================================================================
#define G1_TA 16384
#define G1_TB 8192
#define G1_STAGE (G1_TA + 2 * G1_TB)     // 32KB
#define G1_NST 3
#define G1_SMEM (G1_NST * G1_STAGE)      // 96KB
#define G1_A  0
#define G1_BH G1_TA
#define G1_BL (G1_TA + G1_TB)

__device__ __forceinline__ void g1_issue_stage(
        const __half* pQh, const __half* pQl,
        int m0, int n0, int k0, uint32_t st, int tid) {
    issue_tile<128, 256>(pQh, m0, D, k0, st + G1_A, tid);
    issue_tile<64, 256>(pQh, n0, D, k0, st + G1_BH, tid);
    issue_tile<64, 256>(pQl, n0, D, k0, st + G1_BL, tid);
    CP_ASYNC_COMMIT();
}

__global__ void __launch_bounds__(256, 2)
gemm_qqt_sym_kernel(const __half* __restrict__ Qh, const __half* __restrict__ Ql,
                    float* __restrict__ S) {
    extern __shared__ char smem[];
    const uint32_t sb = smem_to_u32(smem);
    const int tid = threadIdx.x, wid = tid >> 5, lid = tid & 31;
    const int b   = blockIdx.z;
    const int bi  = c_ti[blockIdx.x];
    const int bj64 = c_tj[blockIdx.x];
    const int m0 = bi * 128;
    const int n0 = bj64 * 64;

    const __half* pQh = Qh + (size_t)b * L * D;
    const __half* pQl = Ql + (size_t)b * L * D;

    const int rowbase = (wid & 3) * 32;
    const int colbase = (wid >> 2) * 32;
    const int lrow = lid & 15;
    const uint32_t lkoff = (uint32_t)((lid >> 4) * 16);

    float acc[2][4][4];
    #pragma unroll
    for (int mt = 0; mt < 2; mt++)
        #pragma unroll
        for (int nt = 0; nt < 4; nt++)
            #pragma unroll
            for (int r = 0; r < 4; r++) acc[mt][nt][r] = 0.0f;

    const int nch = D >> 6;   // 4
    g1_issue_stage(pQh, pQl, m0, n0, 0, sb, tid);
    g1_issue_stage(pQh, pQl, m0, n0, 64, sb + G1_STAGE, tid);

    for (int c = 0; c < nch; c++) {
        if (c + 1 < nch) { CP_ASYNC_WAIT(1); } else { CP_ASYNC_WAIT(0); }
        __syncthreads();
        if (c + 2 < nch) {
            g1_issue_stage(pQh, pQl, m0, n0, (c + 2) << 6,
                           sb + (uint32_t)((c + 2) % G1_NST) * G1_STAGE, tid);
        }

        const uint32_t st = sb + (uint32_t)(c % G1_NST) * G1_STAGE;
        const uint32_t aA = st + G1_A;
        const uint32_t bH = st + G1_BH;
        const uint32_t bL = st + G1_BL;

        #pragma unroll
        for (int ks = 0; ks < 4; ks++) {
            const uint32_t kb = (uint32_t)(ks * 32) + lkoff;
            uint32_t ah[2][4];
            #pragma unroll
            for (int mt = 0; mt < 2; mt++) {
                const uint32_t boff = (uint32_t)((rowbase + mt * 16 + lrow) * 128) + kb;
                ldsm_x4(ah[mt][0], ah[mt][1], ah[mt][2], ah[mt][3], aA + SWZ(boff));
            }
            #pragma unroll
            for (int np = 0; np < 2; np++) {
                const uint32_t boff = (uint32_t)((colbase + np * 16 + lrow) * 128) + kb;
                uint32_t bh[4], bl[4];
                ldsm_x4(bh[0], bh[1], bh[2], bh[3], bH + SWZ(boff));
                ldsm_x4(bl[0], bl[1], bl[2], bl[3], bL + SWZ(boff));
                #pragma unroll
                for (int mt = 0; mt < 2; mt++) {
                    float* c0 = acc[mt][np * 2 + 0];
                    float* c1 = acc[mt][np * 2 + 1];
                    mma_f16(c0[0], c0[1], c0[2], c0[3],
                            ah[mt][0], ah[mt][1], ah[mt][2], ah[mt][3], bh[0], bh[2]);
                    mma_f16(c1[0], c1[1], c1[2], c1[3],
                            ah[mt][0], ah[mt][1], ah[mt][2], ah[mt][3], bh[1], bh[3]);
                    mma_f16(c0[0], c0[1], c0[2], c0[3],
                            ah[mt][0], ah[mt][1], ah[mt][2], ah[mt][3], bl[0], bl[2]);
                    mma_f16(c1[0], c1[1], c1[2], c1[3],
                            ah[mt][0], ah[mt][1], ah[mt][2], ah[mt][3], bl[1], bl[3]);
                }
            }
        }
    }
    __syncthreads();

    #pragma unroll
    for (int mt = 0; mt < 2; mt++)
        #pragma unroll
        for (int nt = 0; nt < 4; nt++)
            #pragma unroll
            for (int r = 0; r < 4; r++) {
                float v = acc[mt][nt][r];
                acc[mt][nt][r] = (v == 0.0f) ? neg_inf() : v * INV_TEMP;
            }

    float* pS = S + (size_t)b * L * L;
    const int trow = lid >> 2;
    const int tcol = (lid & 3) * 2;

    #pragma unroll
    for (int mt = 0; mt < 2; mt++) {
        #pragma unroll
        for (int nt = 0; nt < 4; nt++) {
            const int row = m0 + rowbase + mt * 16 + trow;
            const int col = n0 + colbase + nt * 8 + tcol;
            *(float2*)(pS + (size_t)row * L + col) =
                make_float2(acc[mt][nt][0], acc[mt][nt][1]);
            *(float2*)(pS + (size_t)(row + 8) * L + col) =
                make_float2(acc[mt][nt][2], acc[mt][nt][3]);
        }
    }

    if ((bj64 >> 1) > bi) {
        float* smemT = (float*)smem;
        #pragma unroll
        for (int mt = 0; mt < 2; mt++) {
            #pragma unroll
            for (int nt = 0; nt < 4; nt++) {
                const int i0 = rowbase + mt * 16 + trow;
                const int j0 = colbase + nt * 8 + tcol;
                smemT[(j0 + 0) * 132 + i0]     = acc[mt][nt][0];
                smemT[(j0 + 1) * 132 + i0]     = acc[mt][nt][1];
                smemT[(j0 + 0) * 132 + i0 + 8] = acc[mt][nt][2];
                smemT[(j0 + 1) * 132 + i0 + 8] = acc[mt][nt][3];
            }
        }
        __syncthreads();
        const int j       = tid >> 2;
        const int quarter = (tid & 3) * 32;
        float* dst = pS + (size_t)(n0 + j) * L + m0 + quarter;
        const float* srcrow = smemT + j * 132 + quarter;
        #pragma unroll
        for (int u = 0; u < 8; u++) {
            *(float4*)(dst + u * 4) = *(const float4*)(srcrow + u * 4);
        }
    }
}

// ===========================================================================
// GEMM2: O = Ph @ qt_h (single term). CTA 64x128, 8 warps (2x4),
// warp tile 32x32, 3-stage. stage = A 8KB + B 16KB = 24KB; 72KB -> 2 CTAs/SM.
// grid (D/128, L/64, B) = (2, 16, 32) = 1024 CTAs.
// ===========================================================================
#define PV_TA 8192
#define PV_TB 16384
#define PV_STAGE (PV_TA + PV_TB)         // 24KB
#define PV_NST 3
#define PV_SMEM (PV_NST * PV_STAGE)      // 72KB
#define PV_A  0
#define PV_B  PV_TA

__device__ __forceinline__ void pv_issue_stage(
        const __half* pPh, const __half* pBh,
        int m0, int n0, int k0, uint32_t st, int tid) {
    issue_tile<64, 256>(pPh, m0, L, k0, st + PV_A, tid);
    issue_tile<128, 256>(pBh, n0, L, k0, st + PV_B, tid);
    CP_ASYNC_COMMIT();
}

__global__ void __launch_bounds__(256, 2)
gemm_pv_kernel(const __half* __restrict__ Ph,
               const __half* __restrict__ Bh,
               float* __restrict__ O) {
    extern __shared__ char smem[];
    const uint32_t sb = smem_to_u32(smem);
    const int tid = threadIdx.x, wid = tid >> 5, lid = tid & 31;
    const int b  = blockIdx.z;
    const int m0 = blockIdx.y * 64;
    const int n0 = blockIdx.x * 128;

    const __half* pPh = Ph + (size_t)b * L * L;
    const __half* pBh = Bh + (size_t)b * D * L;

    const int rowbase = (wid & 1) * 32;
    const int colbase = (wid >> 1) * 32;
    const int lrow = lid & 15;
    const uint32_t lkoff = (uint32_t)((lid >> 4) * 16);

    float acc[2][4][4];
    #pragma unroll
    for (int mt = 0; mt < 2; mt++)
        #pragma unroll
        for (int nt = 0; nt < 4; nt++)
            #pragma unroll
            for (int r = 0; r < 4; r++) acc[mt][nt][r] = 0.0f;

    const int nch = L >> 6;   // 16

    pv_issue_stage(pPh, pBh, m0, n0, 0, sb, tid);
    pv_issue_stage(pPh, pBh, m0, n0, 64, sb + PV_STAGE, tid);

    for (int c = 0; c < nch; c++) {
        if (c + 1 < nch) { CP_ASYNC_WAIT(1); } else { CP_ASYNC_WAIT(0); }
        __syncthreads();
        if (c + 2 < nch) {
            pv_issue_stage(pPh, pBh, m0, n0, (c + 2) << 6,
                           sb + (uint32_t)((c + 2) % PV_NST) * PV_STAGE, tid);
        }

        const uint32_t st = sb + (uint32_t)(c % PV_NST) * PV_STAGE;
        const uint32_t aA = st + PV_A;
        const uint32_t bB = st + PV_B;

        #pragma unroll
        for (int ks = 0; ks < 4; ks++) {
            const uint32_t kb = (uint32_t)(ks * 32) + lkoff;
            uint32_t ah[2][4];
            #pragma unroll
            for (int mt = 0; mt < 2; mt++) {
                const uint32_t boff = (uint32_t)((rowbase + mt * 16 + lrow) * 128) + kb;
                ldsm_x4(ah[mt][0], ah[mt][1], ah[mt][2], ah[mt][3], aA + SWZ(boff));
            }
            #pragma unroll
            for (int np = 0; np < 2; np++) {
                const uint32_t boff = (uint32_t)((colbase + np * 16 + lrow) * 128) + kb;
                uint32_t bh[4];
                ldsm_x4(bh[0], bh[1], bh[2], bh[3], bB + SWZ(boff));
                #pragma unroll
                for (int mt = 0; mt < 2; mt++) {
                    float* c0 = acc[mt][np * 2 + 0];
                    float* c1 = acc[mt][np * 2 + 1];
                    mma_f16(c0[0], c0[1], c0[2], c0[3],
                            ah[mt][0], ah[mt][1], ah[mt][2], ah[mt][3], bh[0], bh[2]);
                    mma_f16(c1[0], c1[1], c1[2], c1[3],
                            ah[mt][0], ah[mt][1], ah[mt][2], ah[mt][3], bh[1], bh[3]);
                }
            }
        }
    }
    __syncthreads();

    float* pO = O + (size_t)b * L * D;
    const int trow = lid >> 2;
    const int tcol = (lid & 3) * 2;
    #pragma unroll
    for (int mt = 0; mt < 2; mt++) {
        #pragma unroll
        for (int nt = 0; nt < 4; nt++) {
            const int row = m0 + rowbase + mt * 16 + trow;
            const int col = n0 + colbase + nt * 8 + tcol;
            *(float2*)(pO + (size_t)row * D + col) =
                make_float2(acc[mt][nt][0], acc[mt][nt][1]);
            *(float2*)(pO + (size_t)(row + 8) * D + col) =
                make_float2(acc[mt][nt][2], acc[mt][nt][3]);
        }
    }
}

// ---------------------------------------------------------------------------
// softmax: one warp per row, barrier-free. Emits P fp32 + fp16.
// ---------------------------------------------------------------------------
__global__ void __launch_bounds__(256) softmax_kernel(float* __restrict__ attn) {
    const int wid = threadIdx.x >> 5, lid = threadIdx.x & 31;
    const size_t row = (size_t)blockIdx.x * 8 + wid;
    float* p = attn + row * L;
    __half* ph = g_ph + row * L;

    float4 v[8];
    #pragma unroll
    for (int i = 0; i < 8; i++) v[i] = ((const float4*)p)[lid + 32 * i];

    float m = neg_inf();
    #pragma unroll
    for (int i = 0; i < 8; i++) {
        m = fmaxf(m, fmaxf(fmaxf(v[i].x, v[i].y), fmaxf(v[i].z, v[i].w)));
    }
    #pragma unroll
    for (int o = 16; o > 0; o >>= 1) m = fmaxf(m, __shfl_xor_sync(0xffffffffu, m, o));

    if (m == neg_inf()) {
        const float4 z4 = make_float4(0.f, 0.f, 0.f, 0.f);
        const uint2 z2 = make_uint2(0u, 0u);
        #pragma unroll
        for (int i = 0; i < 8; i++) {
            ((float4*)p)[lid + 32 * i] = z4;
            ((uint2*)ph)[lid + 32 * i] = z2;
        }
        return;
    }

    float s = 0.0f;
    #pragma unroll
    for (int i = 0; i < 8; i++) {
        v[i].x = __expf(v[i].x - m);
        v[i].y = __expf(v[i].y - m);
        v[i].z = __expf(v[i].z - m);
        v[i].w = __expf(v[i].w - m);
        s += (v[i].x + v[i].y) + (v[i].z + v[i].w);
    }
    #pragma unroll
    for (int o = 16; o > 0; o >>= 1) s += __shfl_xor_sync(0xffffffffu, s, o);
    const float inv = 1.0f / s;

    #pragma unroll
    for (int i = 0; i < 8; i++) {
        v[i].x *= inv; v[i].y *= inv; v[i].z *= inv; v[i].w *= inv;
        ((float4*)p)[lid + 32 * i] = v[i];

        __half2 hp0 = __floats2half2_rn(v[i].x, v[i].y);
        __half2 hp1 = __floats2half2_rn(v[i].z, v[i].w);
        uint2 hu;
        hu.x = *(uint32_t*)&hp0;
        hu.y = *(uint32_t*)&hp1;
        ((uint2*)ph)[lid + 32 * i] = hu;
    }
}

// ---------------------------------------------------------------------------
// Launch
// ---------------------------------------------------------------------------
extern "C" void kernel_launch(void* const* d_in, const int* in_sizes, int n_in,
                              void* d_out, int out_size) {
    const float* q = (const float*)d_in[0];
    float* out  = (float*)d_out;
    float* attn = (float*)d_out + (size_t)B * L * D;

    void *qh, *ql, *qth, *ph;
    cudaGetSymbolAddress(&qh,  g_qh);
    cudaGetSymbolAddress(&ql,  g_ql);
    cudaGetSymbolAddress(&qth, g_qth);
    cudaGetSymbolAddress(&ph,  g_ph);

    cudaFuncSetAttribute(gemm_qqt_sym_kernel, cudaFuncAttributeMaxDynamicSharedMemorySize, G1_SMEM);
    cudaFuncSetAttribute(gemm_pv_kernel,      cudaFuncAttributeMaxDynamicSharedMemorySize, PV_SMEM);

    dim3 gs(D / 32, L / 32, B);
    split_q_kernel<<<gs, dim3(32, 8)>>>(q);

    dim3 g1(72, 1, B);
    gemm_qqt_sym_kernel<<<g1, 256, G1_SMEM>>>(
        (const __half*)qh, (const __half*)ql, attn);

    softmax_kernel<<<B * L / 8, 256>>>(attn);

    dim3 g2(D / 128, L / 64, B);
    gemm_pv_kernel<<<g2, 256, PV_SMEM>>>(
        (const __half*)ph, (const __half*)qth, out);
}

// round 16
// speedup vs baseline: 1.0862x; 1.0104x over previous
#include <cuda_runtime.h>
#include <cuda_fp16.h>
#include <cstdint>

#define B   32
#define L   1024
#define D   256
#define INV_TEMP (1.0f/16.0f)

// ---------------------------------------------------------------------------
// Scratch (fp16)
// ---------------------------------------------------------------------------
__device__ __half g_qh [B * L * D];
__device__ __half g_ql [B * L * D];
__device__ __half g_qth[B * D * L];
__device__ __half g_ph [B * L * L];   // logits fp16 (gemm1 out) -> P fp16 (softmax out, in place)

// symmetric tile decode: 128-row block i, 64-col block j64, j64 >= 2i (72 tiles)
__constant__ uint8_t c_ti[72] = {
    0,0,0,0,0,0,0,0,0,0,0,0,0,0,0,0,
    1,1,1,1,1,1,1,1,1,1,1,1,1,1,
    2,2,2,2,2,2,2,2,2,2,2,2,
    3,3,3,3,3,3,3,3,3,3,
    4,4,4,4,4,4,4,4,
    5,5,5,5,5,5,
    6,6,6,6,
    7,7};
__constant__ uint8_t c_tj[72] = {
    0,1,2,3,4,5,6,7,8,9,10,11,12,13,14,15,
    2,3,4,5,6,7,8,9,10,11,12,13,14,15,
    4,5,6,7,8,9,10,11,12,13,14,15,
    6,7,8,9,10,11,12,13,14,15,
    8,9,10,11,12,13,14,15,
    10,11,12,13,14,15,
    12,13,14,15,
    14,15};

__device__ __forceinline__ float neg_inf() { return __int_as_float(0xff800000); }

__device__ __forceinline__ uint32_t smem_to_u32(const void* p) {
    uint32_t a;
    asm("{ .reg .u64 t; cvta.to.shared.u64 t, %1; cvt.u32.u64 %0, t; }" : "=r"(a) : "l"(p));
    return a;
}

#define SWZ(x) ((x) ^ (((x) >> 3) & 0x70))

__device__ __forceinline__ void ldsm_x4(uint32_t& r0, uint32_t& r1, uint32_t& r2, uint32_t& r3,
                                        uint32_t addr) {
    asm volatile("ldmatrix.sync.aligned.m8n8.x4.shared.b16 {%0,%1,%2,%3}, [%4];"
                 : "=r"(r0), "=r"(r1), "=r"(r2), "=r"(r3) : "r"(addr));
}

__device__ __forceinline__ void mma_f16(float& c0, float& c1, float& c2, float& c3,
                                        uint32_t a0, uint32_t a1, uint32_t a2, uint32_t a3,
                                        uint32_t b0, uint32_t b1) {
    asm volatile("mma.sync.aligned.m16n8k16.row.col.f32.f16.f16.f32 "
                 "{%0,%1,%2,%3}, {%4,%5,%6,%7}, {%8,%9}, {%0,%1,%2,%3};"
                 : "+f"(c0), "+f"(c1), "+f"(c2), "+f"(c3)
                 : "r"(a0), "r"(a1), "r"(a2), "r"(a3), "r"(b0), "r"(b1));
}

#define CP_ASYNC_16(dst, src) \
    asm volatile("cp.async.cg.shared.global [%0], [%1], 16;" :: "r"(dst), "l"(src))
#define CP_ASYNC_COMMIT() asm volatile("cp.async.commit_group;" ::: "memory")
#define CP_ASYNC_WAIT(n)  asm volatile("cp.async.wait_group %0;" :: "n"(n) : "memory")

// ---------------------------------------------------------------------------
// Kernel A: split q -> fp16 hi/lo + transposed hi copy.
// ---------------------------------------------------------------------------
__global__ void __launch_bounds__(256) split_q_kernel(const float* __restrict__ q) {
    const int b  = blockIdx.z;
    const int d0 = blockIdx.x * 32;
    const int l0 = blockIdx.y * 32;
    const float* Q = q + (size_t)b * L * D;
    __shared__ float t[32][33];
    const int tx = threadIdx.x, ty = threadIdx.y;

    #pragma unroll
    for (int i = 0; i < 4; i++) {
        const int r = ty + i * 8;
        const float v = Q[(size_t)(l0 + r) * D + d0 + tx];
        t[r][tx] = v;
        __half h  = __float2half_rn(v);
        __half lo = __float2half_rn(v - __half2float(h));
        const size_t idx = (size_t)b * L * D + (size_t)(l0 + r) * D + d0 + tx;
        g_qh[idx] = h;
        g_ql[idx] = lo;
    }
    __syncthreads();
    #pragma unroll
    for (int i = 0; i < 4; i++) {
        const int r = ty + i * 8;
        const float v = t[tx][r];
        const size_t idx = (size_t)b * D * L + (size_t)(d0 + r) * L + l0 + tx;
        g_qth[idx] = __float2half_rn(v);
    }
}

// ---------------------------------------------------------------------------
// Generic tile loader: ROWS x 64 fp16, 128B swizzled rows, NT threads.
// ---------------------------------------------------------------------------
template <int ROWS, int NT>
__device__ __forceinline__ void issue_tile(const __half* __restrict__ src,
                                           int row0, int ld, int k0,
                                           uint32_t smem_tile, int tid) {
    #pragma unroll
    for (int i = 0; i < (ROWS * 8) / NT; i++) {
        const int chunk = tid + i * NT;
        const int row = chunk >> 3;
        const int c16 = chunk & 7;
        const __half* g = src + (size_t)(row0 + row) * ld + k0 + c16 * 8;
        CP_ASYNC_16(smem_tile + SWZ((uint32_t)(row * 128 + c16 * 16)), g);
    }
}

// ===========================================================================
// GEMM1 (symmetric): logits = mask(Q@Q^T)/16 stored as FP16 into g_ph.
// 2-term fp16 (qh @ qh + qh @ ql == qh @ q). CTA tile 128x64, 8 warps (4x2),
// warp tile 32x32, 3-stage, 96KB -> 2 CTAs/SM. grid (72, 1, B).
// ===========================================================================
#define G1_TA 16384
#define G1_TB 8192
#define G1_STAGE (G1_TA + 2 * G1_TB)     // 32KB
#define G1_NST 3
#define G1_SMEM (G1_NST * G1_STAGE)      // 96KB
#define G1_A  0
#define G1_BH G1_TA
#define G1_BL (G1_TA + G1_TB)

__device__ __forceinline__ void g1_issue_stage(
        const __half* pQh, const __half* pQl,
        int m0, int n0, int k0, uint32_t st, int tid) {
    issue_tile<128, 256>(pQh, m0, D, k0, st + G1_A, tid);
    issue_tile<64, 256>(pQh, n0, D, k0, st + G1_BH, tid);
    issue_tile<64, 256>(pQl, n0, D, k0, st + G1_BL, tid);
    CP_ASYNC_COMMIT();
}

__global__ void __launch_bounds__(256, 2)
gemm_qqt_sym_kernel(const __half* __restrict__ Qh, const __half* __restrict__ Ql,
                    __half* __restrict__ Sh) {
    extern __shared__ char smem[];
    const uint32_t sb = smem_to_u32(smem);
    const int tid = threadIdx.x, wid = tid >> 5, lid = tid & 31;
    const int b   = blockIdx.z;
    const int bi  = c_ti[blockIdx.x];
    const int bj64 = c_tj[blockIdx.x];
    const int m0 = bi * 128;
    const int n0 = bj64 * 64;

    const __half* pQh = Qh + (size_t)b * L * D;
    const __half* pQl = Ql + (size_t)b * L * D;

    const int rowbase = (wid & 3) * 32;
    const int colbase = (wid >> 2) * 32;
    const int lrow = lid & 15;
    const uint32_t lkoff = (uint32_t)((lid >> 4) * 16);

    float acc[2][4][4];
    #pragma unroll
    for (int mt = 0; mt < 2; mt++)
        #pragma unroll
        for (int nt = 0; nt < 4; nt++)
            #pragma unroll
            for (int r = 0; r < 4; r++) acc[mt][nt][r] = 0.0f;

    const int nch = D >> 6;   // 4
    g1_issue_stage(pQh, pQl, m0, n0, 0, sb, tid);
    g1_issue_stage(pQh, pQl, m0, n0, 64, sb + G1_STAGE, tid);

    for (int c = 0; c < nch; c++) {
        if (c + 1 < nch) { CP_ASYNC_WAIT(1); } else { CP_ASYNC_WAIT(0); }
        __syncthreads();
        if (c + 2 < nch) {
            g1_issue_stage(pQh, pQl, m0, n0, (c + 2) << 6,
                           sb + (uint32_t)((c + 2) % G1_NST) * G1_STAGE, tid);
        }

        const uint32_t st = sb + (uint32_t)(c % G1_NST) * G1_STAGE;
        const uint32_t aA = st + G1_A;
        const uint32_t bH = st + G1_BH;
        const uint32_t bL = st + G1_BL;

        #pragma unroll
        for (int ks = 0; ks < 4; ks++) {
            const uint32_t kb = (uint32_t)(ks * 32) + lkoff;
            uint32_t ah[2][4];
            #pragma unroll
            for (int mt = 0; mt < 2; mt++) {
                const uint32_t boff = (uint32_t)((rowbase + mt * 16 + lrow) * 128) + kb;
                ldsm_x4(ah[mt][0], ah[mt][1], ah[mt][2], ah[mt][3], aA + SWZ(boff));
            }
            #pragma unroll
            for (int np = 0; np < 2; np++) {
                const uint32_t boff = (uint32_t)((colbase + np * 16 + lrow) * 128) + kb;
                uint32_t bh[4], bl[4];
                ldsm_x4(bh[0], bh[1], bh[2], bh[3], bH + SWZ(boff));
                ldsm_x4(bl[0], bl[1], bl[2], bl[3], bL + SWZ(boff));
                #pragma unroll
                for (int mt = 0; mt < 2; mt++) {
                    float* c0 = acc[mt][np * 2 + 0];
                    float* c1 = acc[mt][np * 2 + 1];
                    mma_f16(c0[0], c0[1], c0[2], c0[3],
                            ah[mt][0], ah[mt][1], ah[mt][2], ah[mt][3], bh[0], bh[2]);
                    mma_f16(c1[0], c1[1], c1[2], c1[3],
                            ah[mt][0], ah[mt][1], ah[mt][2], ah[mt][3], bh[1], bh[3]);
                    mma_f16(c0[0], c0[1], c0[2], c0[3],
                            ah[mt][0], ah[mt][1], ah[mt][2], ah[mt][3], bl[0], bl[2]);
                    mma_f16(c1[0], c1[1], c1[2], c1[3],
                            ah[mt][0], ah[mt][1], ah[mt][2], ah[mt][3], bl[1], bl[3]);
                }
            }
        }
    }
    __syncthreads();

    // mask + scale
    #pragma unroll
    for (int mt = 0; mt < 2; mt++)
        #pragma unroll
        for (int nt = 0; nt < 4; nt++)
            #pragma unroll
            for (int r = 0; r < 4; r++) {
                float v = acc[mt][nt][r];
                acc[mt][nt][r] = (v == 0.0f) ? neg_inf() : v * INV_TEMP;
            }

    __half* pSh = Sh + (size_t)b * L * L;
    const int trow = lid >> 2;
    const int tcol = (lid & 3) * 2;

    // direct write (fp16)
    #pragma unroll
    for (int mt = 0; mt < 2; mt++) {
        #pragma unroll
        for (int nt = 0; nt < 4; nt++) {
            const int row = m0 + rowbase + mt * 16 + trow;
            const int col = n0 + colbase + nt * 8 + tcol;
            __half2 v01 = __floats2half2_rn(acc[mt][nt][0], acc[mt][nt][1]);
            __half2 v23 = __floats2half2_rn(acc[mt][nt][2], acc[mt][nt][3]);
            *(__half2*)(pSh + (size_t)row * L + col)       = v01;
            *(__half2*)(pSh + (size_t)(row + 8) * L + col) = v23;
        }
    }

    if ((bj64 >> 1) > bi) {
        // mirror write: stage transpose fp32 in smem, convert at store
        float* smemT = (float*)smem;
        #pragma unroll
        for (int mt = 0; mt < 2; mt++) {
            #pragma unroll
            for (int nt = 0; nt < 4; nt++) {
                const int i0 = rowbase + mt * 16 + trow;
                const int j0 = colbase + nt * 8 + tcol;
                smemT[(j0 + 0) * 132 + i0]     = acc[mt][nt][0];
                smemT[(j0 + 1) * 132 + i0]     = acc[mt][nt][1];
                smemT[(j0 + 0) * 132 + i0 + 8] = acc[mt][nt][2];
                smemT[(j0 + 1) * 132 + i0 + 8] = acc[mt][nt][3];
            }
        }
        __syncthreads();
        const int j       = tid >> 2;            // 0..63
        const int quarter = (tid & 3) * 32;      // 0,32,64,96
        __half* dst = pSh + (size_t)(n0 + j) * L + m0 + quarter;
        const float* srcrow = smemT + j * 132 + quarter;
        #pragma unroll
        for (int u = 0; u < 16; u++) {
            __half2 hv = __floats2half2_rn(srcrow[u * 2], srcrow[u * 2 + 1]);
            *(__half2*)(dst + u * 2) = hv;
        }
    }
}

// ===========================================================================
// GEMM2: O = Ph @ qt_h (single term). CTA 64x128, 8 warps (2x4),
// warp tile 32x32, 3-stage, 72KB -> 2 CTAs/SM. grid (2, 16, 32).
// ===========================================================================
#define PV_TA 8192
#define PV_TB 16384
#define PV_STAGE (PV_TA + PV_TB)         // 24KB
#define PV_NST 3
#define PV_SMEM (PV_NST * PV_STAGE)      // 72KB
#define PV_A  0
#define PV_B  PV_TA

__device__ __forceinline__ void pv_issue_stage(
        const __half* pPh, const __half* pBh,
        int m0, int n0, int k0, uint32_t st, int tid) {
    issue_tile<64, 256>(pPh, m0, L, k0, st + PV_A, tid);
    issue_tile<128, 256>(pBh, n0, L, k0, st + PV_B, tid);
    CP_ASYNC_COMMIT();
}

__global__ void __launch_bounds__(256, 2)
gemm_pv_kernel(const __half* __restrict__ Ph,
               const __half* __restrict__ Bh,
               float* __restrict__ O) {
    extern __shared__ char smem[];
    const uint32_t sb = smem_to_u32(smem);
    const int tid = threadIdx.x, wid = tid >> 5, lid = tid & 31;
    const int b  = blockIdx.z;
    const int m0 = blockIdx.y * 64;
    const int n0 = blockIdx.x * 128;

    const __half* pPh = Ph + (size_t)b * L * L;
    const __half* pBh = Bh + (size_t)b * D * L;

    const int rowbase = (wid & 1) * 32;
    const int colbase = (wid >> 1) * 32;
    const int lrow = lid & 15;
    const uint32_t lkoff = (uint32_t)((lid >> 4) * 16);

    float acc[2][4][4];
    #pragma unroll
    for (int mt = 0; mt < 2; mt++)
        #pragma unroll
        for (int nt = 0; nt < 4; nt++)
            #pragma unroll
            for (int r = 0; r < 4; r++) acc[mt][nt][r] = 0.0f;

    const int nch = L >> 6;   // 16

    pv_issue_stage(pPh, pBh, m0, n0, 0, sb, tid);
    pv_issue_stage(pPh, pBh, m0, n0, 64, sb + PV_STAGE, tid);

    for (int c = 0; c < nch; c++) {
        if (c + 1 < nch) { CP_ASYNC_WAIT(1); } else { CP_ASYNC_WAIT(0); }
        __syncthreads();
        if (c + 2 < nch) {
            pv_issue_stage(pPh, pBh, m0, n0, (c + 2) << 6,
                           sb + (uint32_t)((c + 2) % PV_NST) * PV_STAGE, tid);
        }

        const uint32_t st = sb + (uint32_t)(c % PV_NST) * PV_STAGE;
        const uint32_t aA = st + PV_A;
        const uint32_t bB = st + PV_B;

        #pragma unroll
        for (int ks = 0; ks < 4; ks++) {
            const uint32_t kb = (uint32_t)(ks * 32) + lkoff;
            uint32_t ah[2][4];
            #pragma unroll
            for (int mt = 0; mt < 2; mt++) {
                const uint32_t boff = (uint32_t)((rowbase + mt * 16 + lrow) * 128) + kb;
                ldsm_x4(ah[mt][0], ah[mt][1], ah[mt][2], ah[mt][3], aA + SWZ(boff));
            }
            #pragma unroll
            for (int np = 0; np < 2; np++) {
                const uint32_t boff = (uint32_t)((colbase + np * 16 + lrow) * 128) + kb;
                uint32_t bh[4];
                ldsm_x4(bh[0], bh[1], bh[2], bh[3], bB + SWZ(boff));
                #pragma unroll
                for (int mt = 0; mt < 2; mt++) {
                    float* c0 = acc[mt][np * 2 + 0];
                    float* c1 = acc[mt][np * 2 + 1];
                    mma_f16(c0[0], c0[1], c0[2], c0[3],
                            ah[mt][0], ah[mt][1], ah[mt][2], ah[mt][3], bh[0], bh[2]);
                    mma_f16(c1[0], c1[1], c1[2], c1[3],
                            ah[mt][0], ah[mt][1], ah[mt][2], ah[mt][3], bh[1], bh[3]);
                }
            }
        }
    }
    __syncthreads();

    float* pO = O + (size_t)b * L * D;
    const int trow = lid >> 2;
    const int tcol = (lid & 3) * 2;
    #pragma unroll
    for (int mt = 0; mt < 2; mt++) {
        #pragma unroll
        for (int nt = 0; nt < 4; nt++) {
            const int row = m0 + rowbase + mt * 16 + trow;
            const int col = n0 + colbase + nt * 8 + tcol;
            *(float2*)(pO + (size_t)row * D + col) =
                make_float2(acc[mt][nt][0], acc[mt][nt][1]);
            *(float2*)(pO + (size_t)(row + 8) * D + col) =
                make_float2(acc[mt][nt][2], acc[mt][nt][3]);
        }
    }
}

// ---------------------------------------------------------------------------
// softmax: one warp per row, barrier-free. READS fp16 logits from g_ph,
// writes attn fp32 to d_out and P fp16 back into g_ph in place.
// ---------------------------------------------------------------------------
__global__ void __launch_bounds__(256) softmax_kernel(float* __restrict__ attn,
                                                      __half* __restrict__ Ph) {
    const int wid = threadIdx.x >> 5, lid = threadIdx.x & 31;
    const size_t row = (size_t)blockIdx.x * 8 + wid;
    float* p = attn + row * L;
    __half* ph = Ph + row * L;

    float4 v[8];
    #pragma unroll
    for (int i = 0; i < 8; i++) {
        uint2 raw = ((const uint2*)ph)[lid + 32 * i];
        __half2 h0 = *(__half2*)&raw.x;
        __half2 h1 = *(__half2*)&raw.y;
        float2 f0 = __half22float2(h0);
        float2 f1 = __half22float2(h1);
        v[i] = make_float4(f0.x, f0.y, f1.x, f1.y);
    }

    float m = neg_inf();
    #pragma unroll
    for (int i = 0; i < 8; i++) {
        m = fmaxf(m, fmaxf(fmaxf(v[i].x, v[i].y), fmaxf(v[i].z, v[i].w)));
    }
    #pragma unroll
    for (int o = 16; o > 0; o >>= 1) m = fmaxf(m, __shfl_xor_sync(0xffffffffu, m, o));

    if (m == neg_inf()) {
        const float4 z4 = make_float4(0.f, 0.f, 0.f, 0.f);
        const uint2 z2 = make_uint2(0u, 0u);
        #pragma unroll
        for (int i = 0; i < 8; i++) {
            ((float4*)p)[lid + 32 * i] = z4;
            ((uint2*)ph)[lid + 32 * i] = z2;
        }
        return;
    }

    float s = 0.0f;
    #pragma unroll
    for (int i = 0; i < 8; i++) {
        v[i].x = __expf(v[i].x - m);
        v[i].y = __expf(v[i].y - m);
        v[i].z = __expf(v[i].z - m);
        v[i].w = __expf(v[i].w - m);
        s += (v[i].x + v[i].y) + (v[i].z + v[i].w);
    }
    #pragma unroll
    for (int o = 16; o > 0; o >>= 1) s += __shfl_xor_sync(0xffffffffu, s, o);
    const float inv = 1.0f / s;

    #pragma unroll
    for (int i = 0; i < 8; i++) {
        v[i].x *= inv; v[i].y *= inv; v[i].z *= inv; v[i].w *= inv;
        ((float4*)p)[lid + 32 * i] = v[i];

        __half2 hp0 = __floats2half2_rn(v[i].x, v[i].y);
        __half2 hp1 = __floats2half2_rn(v[i].z, v[i].w);
        uint2 hu;
        hu.x = *(uint32_t*)&hp0;
        hu.y = *(uint32_t*)&hp1;
        ((uint2*)ph)[lid + 32 * i] = hu;
    }
}

// ---------------------------------------------------------------------------
// Launch
// ---------------------------------------------------------------------------
extern "C" void kernel_launch(void* const* d_in, const int* in_sizes, int n_in,
                              void* d_out, int out_size) {
    const float* q = (const float*)d_in[0];
    float* out  = (float*)d_out;
    float* attn = (float*)d_out + (size_t)B * L * D;

    void *qh, *ql, *qth, *ph;
    cudaGetSymbolAddress(&qh,  g_qh);
    cudaGetSymbolAddress(&ql,  g_ql);
    cudaGetSymbolAddress(&qth, g_qth);
    cudaGetSymbolAddress(&ph,  g_ph);

    cudaFuncSetAttribute(gemm_qqt_sym_kernel, cudaFuncAttributeMaxDynamicSharedMemorySize, G1_SMEM);
    cudaFuncSetAttribute(gemm_pv_kernel,      cudaFuncAttributeMaxDynamicSharedMemorySize, PV_SMEM);

    dim3 gs(D / 32, L / 32, B);
    split_q_kernel<<<gs, dim3(32, 8)>>>(q);

    // GEMM1 -> fp16 logits into g_ph
    dim3 g1(72, 1, B);
    gemm_qqt_sym_kernel<<<g1, 256, G1_SMEM>>>(
        (const __half*)qh, (const __half*)ql, (__half*)ph);

    // softmax: fp16 logits -> attn fp32 (d_out) + P fp16 (g_ph, in place)
    softmax_kernel<<<B * L / 8, 256>>>(attn, (__half*)ph);

    // GEMM2: O = P @ Q
    dim3 g2(D / 128, L / 64, B);
    gemm_pv_kernel<<<g2, 256, PV_SMEM>>>(
        (const __half*)ph, (const __half*)qth, out);
}